// round 16
// baseline (speedup 1.0000x reference)
#include <cuda_runtime.h>
#include <cuda_fp16.h>
#include <cstdint>

// ---------------- problem constants ----------------
#define NMAX    8192
#define DDIM    128
#define TM      128
#define NTILES  (NMAX / TM)           // 64
#define CC      14.426950408889634f   // log2(e) / TEMPERATURE(=0.1)
#define LN2F    0.69314718055994531f
#define SKIP_T  25.0f

#define TILE_BYTES (TM * DDIM * 2)    // 32 KB fp16

// smem layout (bytes) — 73216 B/CTA: 3 CTAs/SM fit in 228 KB
#define OFF_A     0
#define OFF_B     (TILE_BYTES)
#define OFF_SROW  (2 * TILE_BYTES)            // 128 f32
#define OFF_SCOL  (OFF_SROW + 512)            // 128 f32
#define OFF_ROWM  (OFF_SCOL + 512)            // 2 x 128 f32
#define OFF_ROWS  (OFF_ROWM + 1024)           // 2 x 128 f32
#define OFF_COLM  (OFF_ROWS + 1024)           // 4 x 128 f32
#define OFF_COLMF (OFF_COLM + 2048)           // 128 f32
#define OFF_COLS  (OFF_COLMF + 512)           // 4 x 128 f32
#define SMEM_K2   (OFF_COLS + 2048)           // 73216

__device__ __align__(16) __half g_thf[NMAX * DDIM];   // t in fp16
__device__ float  g_sC[NMAX];             // s_i * CC
__device__ float  g_dlabE[NMAX];          // |s_i - u_i| * CC
__device__ __align__(16) float2 g_c[NMAX * NTILES];   // [row][slot] = (max, sum)
__device__ float  g_sum;
__device__ int    g_count;

// ---------------- low-level helpers ----------------
__device__ __forceinline__ float ex2f(float x) {
    float r;
    asm("ex2.approx.f32 %0, %1;" : "=f"(r) : "f"(x));
    return r;
}
__device__ __forceinline__ float lg2f(float x) {
    float r;
    asm("lg2.approx.f32 %0, %1;" : "=f"(r) : "f"(x));
    return r;
}
__device__ __forceinline__ uint32_t smem_u32(const void* p) {
    uint32_t a;
    asm("{ .reg .u64 t; cvta.to.shared.u64 t, %1; cvt.u32.u64 %0, t; }" : "=r"(a) : "l"(p));
    return a;
}
__device__ __forceinline__ void cp_async16(uint32_t dst, const void* src) {
    asm volatile("cp.async.cg.shared.global [%0], [%1], 16;" :: "r"(dst), "l"(src) : "memory");
}
#define CP_COMMIT() asm volatile("cp.async.commit_group;" ::: "memory")
#define CP_WAIT0()  asm volatile("cp.async.wait_group 0;" ::: "memory")

#define LDSM_X4(r, addr)                                                      \
    asm volatile("ldmatrix.sync.aligned.m8n8.x4.shared.b16 {%0,%1,%2,%3}, [%4];" \
        : "=r"((r)[0]), "=r"((r)[1]), "=r"((r)[2]), "=r"((r)[3]) : "r"(addr))

// fp16 inputs, fp16 accumulators (2 b32 regs = 4 halves)
__device__ __forceinline__ void mma16816h(uint32_t* c, const uint32_t* a,
                                          uint32_t b0, uint32_t b1) {
    asm volatile(
        "mma.sync.aligned.m16n8k16.row.col.f16.f16.f16.f16 "
        "{%0,%1}, {%2,%3,%4,%5}, {%6,%7}, {%0,%1};"
        : "+r"(c[0]), "+r"(c[1])
        : "r"(a[0]), "r"(a[1]), "r"(a[2]), "r"(a[3]), "r"(b0), "r"(b1));
}
__device__ __forceinline__ uint32_t swz(int r, int c) {
    return (uint32_t)(r * 256 + ((c ^ (r & 7)) << 4));
}
__device__ __forceinline__ float2 h2f2(uint32_t h) {
    return __half22float2(*reinterpret_cast<__half2*>(&h));
}

// ---------------- K1: per-row scalars + t -> fp16 (R10 verbatim) ----------
__global__ void k1_rowprep(const float* __restrict__ q, const float* __restrict__ t,
                           const int* __restrict__ label, const int* __restrict__ jidx,
                           int n) {
    if (blockIdx.x == 0 && threadIdx.x == 0) { g_sum = 0.f; g_count = 0; }
    int i = blockIdx.x * 8 + (threadIdx.x >> 5);
    if (i >= n) return;
    int lane = threadIdx.x & 31;
    int j = jidx[i];

    float4 a = reinterpret_cast<const float4*>(q + (size_t)i * DDIM)[lane];
    float4 b = reinterpret_cast<const float4*>(q + (size_t)j * DDIM)[lane];
    float s = a.x * b.x + a.y * b.y + a.z * b.z + a.w * b.w;
    #pragma unroll
    for (int o = 16; o; o >>= 1) s += __shfl_xor_sync(0xFFFFFFFFu, s, o);

    int l = label[i];
    int col;
    if (l == i)       col = j;
    else if (j > i)   col = (l > i && l <= j) ? l - 1 : l;
    else              col = (l >= j && l < i) ? l + 1 : l;

    float4 c = reinterpret_cast<const float4*>(t + (size_t)i   * DDIM)[lane];
    float4 d = reinterpret_cast<const float4*>(t + (size_t)col * DDIM)[lane];
    float u = c.x * d.x + c.y * d.y + c.z * d.z + c.w * d.w;
    #pragma unroll
    for (int o = 16; o; o >>= 1) u += __shfl_xor_sync(0xFFFFFFFFu, u, o);

    __half2 p0 = __floats2half2_rn(c.x, c.y);
    __half2 p1 = __floats2half2_rn(c.z, c.w);
    uint2 pk;
    pk.x = *reinterpret_cast<uint32_t*>(&p0);
    pk.y = *reinterpret_cast<uint32_t*>(&p1);
    reinterpret_cast<uint2*>(g_thf + (size_t)i * DDIM)[lane] = pk;

    if (lane == 0) {
        g_sC[i]    = s * CC;
        g_dlabE[i] = fabsf(s - u) * CC;
    }
}

// ---------------- K2: R10 kernel, 3 CTAs/SM (occupancy experiment) ----------
__global__ void __launch_bounds__(256, 3) k2_sym(int ntiles) {
    extern __shared__ char smem[];
    const int tid = threadIdx.x, wid = tid >> 5, lane = tid & 31;
    const int wr = wid & 3;          // warp row group (32 rows)
    const int wc = wid >> 2;         // warp col group (64 cols)
    const int g = lane >> 2, tig = lane & 3;

    // decode blockIdx -> (I, J), I <= J
    int b = blockIdx.x;
    int I;
    {
        float nn = 2.0f * ntiles + 1.0f;
        I = (int)((nn - sqrtf(nn * nn - 8.0f * (float)b)) * 0.5f);
        if (I < 0) I = 0;
        while ((I + 1) * ntiles - ((I + 1) * I) / 2 <= b) ++I;
        while (I * ntiles - (I * (I - 1)) / 2 > b) --I;
    }
    const int J = I + (b - (I * ntiles - (I * (I - 1)) / 2));
    const bool diag = (I == J);
    const int row0 = I * TM, col0 = J * TM;

    const uint32_t sA = smem_u32(smem);
    const uint32_t sB = diag ? sA : (sA + OFF_B);
    float* sRowBuf = reinterpret_cast<float*>(smem + OFF_SROW);
    float* sColBuf = reinterpret_cast<float*>(smem + OFF_SCOL);
    float* rowMbuf = reinterpret_cast<float*>(smem + OFF_ROWM);
    float* rowSbuf = reinterpret_cast<float*>(smem + OFF_ROWS);
    float* colMbuf = reinterpret_cast<float*>(smem + OFF_COLM);
    float* colMF   = reinterpret_cast<float*>(smem + OFF_COLMF);
    float* colSbuf = reinterpret_cast<float*>(smem + OFF_COLS);

    // ---- stage tiles + s vectors ----
    {
        const char* Ag = (const char*)(g_thf + (size_t)row0 * DDIM);
        for (int idx = tid; idx < 2048; idx += 256)
            cp_async16(sA + swz(idx >> 4, idx & 15), Ag + idx * 16);
        if (!diag) {
            const char* Bg = (const char*)(g_thf + (size_t)col0 * DDIM);
            for (int idx = tid; idx < 2048; idx += 256)
                cp_async16(sA + OFF_B + swz(idx >> 4, idx & 15), Bg + idx * 16);
        }
        if (tid < 128) sRowBuf[tid] = g_sC[row0 + tid];
        else           sColBuf[tid - 128] = g_sC[col0 + tid - 128];
        CP_COMMIT();
        CP_WAIT0();
        __syncthreads();
    }

    // ---- 128x128x128 MMA: warp does 32x64, frags 2(M) x 8(N), fp16 acc ----
    uint32_t acc[2][8][2];
    #pragma unroll
    for (int mf = 0; mf < 2; mf++)
        #pragma unroll
        for (int nf = 0; nf < 8; nf++) {
            acc[mf][nf][0] = 0u;
            acc[mf][nf][1] = 0u;
        }

    #pragma unroll
    for (int kc = 0; kc < 8; kc++) {
        uint32_t a0[4], a1[4];
        {
            int r = wr * 32 + (lane & 15);
            int c = kc * 2 + (lane >> 4);
            LDSM_X4(a0, sA + swz(r, c));
            LDSM_X4(a1, sA + swz(r + 16, c));
        }
        #pragma unroll
        for (int p = 0; p < 4; p++) {
            uint32_t bb[4];
            int r = wc * 64 + p * 16 + ((lane >> 4) << 3) + (lane & 7);
            int c = kc * 2 + ((lane >> 3) & 1);
            LDSM_X4(bb, sB + swz(r, c));
            mma16816h(acc[0][2 * p],     a0, bb[0], bb[1]);
            mma16816h(acc[0][2 * p + 1], a0, bb[2], bb[3]);
            mma16816h(acc[1][2 * p],     a1, bb[0], bb[1]);
            mma16816h(acc[1][2 * p + 1], a1, bb[2], bb[3]);
        }
    }

    // frag coords: reg rr (0/1): row_local = wr*32 + mf*16 + rr*8 + g
    //              half h (lo/hi): col_local = wc*64 + nf*8 + tig*2 + h

    // ======== ROW PASS (rows of tile I, s = sRow, slot J) ========
    float sRow[4], rM[4], Mrow[4], rS[4];
    #pragma unroll
    for (int qq = 0; qq < 4; qq++) {
        sRow[qq] = sRowBuf[wr * 32 + (qq >> 1) * 16 + (qq & 1) * 8 + g];
        rM[qq] = -1e30f;
    }
    #pragma unroll
    for (int mf = 0; mf < 2; mf++)
        #pragma unroll
        for (int nf = 0; nf < 8; nf++)
            #pragma unroll
            for (int rr = 0; rr < 2; rr++) {
                int qq = mf * 2 + rr;
                float2 v = h2f2(acc[mf][nf][rr]);
                rM[qq] = fmaxf(rM[qq], fabsf(fmaf(v.x, -CC, sRow[qq])));
                rM[qq] = fmaxf(rM[qq], fabsf(fmaf(v.y, -CC, sRow[qq])));
            }
    #pragma unroll
    for (int qq = 0; qq < 4; qq++) {
        rM[qq] = fmaxf(rM[qq], __shfl_xor_sync(0xFFFFFFFFu, rM[qq], 1));
        rM[qq] = fmaxf(rM[qq], __shfl_xor_sync(0xFFFFFFFFu, rM[qq], 2));
    }
    if (tig == 0) {
        #pragma unroll
        for (int qq = 0; qq < 4; qq++)
            rowMbuf[wc * 128 + wr * 32 + (qq >> 1) * 16 + (qq & 1) * 8 + g] = rM[qq];
    }
    __syncthreads();
    #pragma unroll
    for (int qq = 0; qq < 4; qq++) {
        float other = rowMbuf[(1 - wc) * 128 + wr * 32 + (qq >> 1) * 16 + (qq & 1) * 8 + g];
        Mrow[qq] = fmaxf(rM[qq], other);
        rS[qq] = 0.f;
    }
    #pragma unroll
    for (int mf = 0; mf < 2; mf++)
        #pragma unroll
        for (int nf = 0; nf < 8; nf++)
            #pragma unroll
            for (int rr = 0; rr < 2; rr++) {
                int qq = mf * 2 + rr;
                float2 v = h2f2(acc[mf][nf][rr]);
                float E0 = fabsf(fmaf(v.x, -CC, sRow[qq]));
                float E1 = fabsf(fmaf(v.y, -CC, sRow[qq]));
                if (E0 > Mrow[qq] - SKIP_T) rS[qq] += ex2f(E0 - Mrow[qq]);
                if (E1 > Mrow[qq] - SKIP_T) rS[qq] += ex2f(E1 - Mrow[qq]);
            }
    #pragma unroll
    for (int qq = 0; qq < 4; qq++) {
        rS[qq] += __shfl_xor_sync(0xFFFFFFFFu, rS[qq], 1);
        rS[qq] += __shfl_xor_sync(0xFFFFFFFFu, rS[qq], 2);
    }
    if (tig == 0) {
        #pragma unroll
        for (int qq = 0; qq < 4; qq++)
            rowSbuf[wc * 128 + wr * 32 + (qq >> 1) * 16 + (qq & 1) * 8 + g] = rS[qq];
    }
    __syncthreads();
    if (wc == 0 && tig == 0) {
        #pragma unroll
        for (int qq = 0; qq < 4; qq++) {
            int rl = wr * 32 + (qq >> 1) * 16 + (qq & 1) * 8 + g;
            float S = rS[qq] + rowSbuf[128 + rl];
            g_c[(size_t)(row0 + rl) * NTILES + J] = make_float2(Mrow[qq], S);
        }
    }

    // ======== COL PASS (rows of tile J, s = sCol, slot I) ========
    if (!diag) {
        float sColv[16], cM[16];
        #pragma unroll
        for (int nf = 0; nf < 8; nf++)
            #pragma unroll
            for (int p = 0; p < 2; p++) {
                sColv[nf * 2 + p] = sColBuf[wc * 64 + nf * 8 + tig * 2 + p];
                cM[nf * 2 + p] = -1e30f;
            }
        #pragma unroll
        for (int mf = 0; mf < 2; mf++)
            #pragma unroll
            for (int nf = 0; nf < 8; nf++)
                #pragma unroll
                for (int rr = 0; rr < 2; rr++) {
                    float2 v = h2f2(acc[mf][nf][rr]);
                    int i0 = nf * 2, i1 = nf * 2 + 1;
                    cM[i0] = fmaxf(cM[i0], fabsf(fmaf(v.x, -CC, sColv[i0])));
                    cM[i1] = fmaxf(cM[i1], fabsf(fmaf(v.y, -CC, sColv[i1])));
                }
        #pragma unroll
        for (int ii = 0; ii < 16; ii++) {
            cM[ii] = fmaxf(cM[ii], __shfl_xor_sync(0xFFFFFFFFu, cM[ii], 4));
            cM[ii] = fmaxf(cM[ii], __shfl_xor_sync(0xFFFFFFFFu, cM[ii], 8));
            cM[ii] = fmaxf(cM[ii], __shfl_xor_sync(0xFFFFFFFFu, cM[ii], 16));
        }
        if (lane < 4) {
            #pragma unroll
            for (int ii = 0; ii < 16; ii++)
                colMbuf[wr * 128 + wc * 64 + (ii >> 1) * 8 + lane * 2 + (ii & 1)] = cM[ii];
        }
        __syncthreads();
        if (wr == 0) {
            #pragma unroll
            for (int rep = 0; rep < 2; rep++) {
                int cl = wc * 64 + lane + rep * 32;
                float m = colMbuf[cl];
                m = fmaxf(m, colMbuf[128 + cl]);
                m = fmaxf(m, colMbuf[256 + cl]);
                m = fmaxf(m, colMbuf[384 + cl]);
                colMF[cl] = m;
            }
        }
        __syncthreads();
        float cS[16], McF[16];
        #pragma unroll
        for (int ii = 0; ii < 16; ii++) {
            McF[ii] = colMF[wc * 64 + (ii >> 1) * 8 + tig * 2 + (ii & 1)];
            cS[ii] = 0.f;
        }
        #pragma unroll
        for (int mf = 0; mf < 2; mf++)
            #pragma unroll
            for (int nf = 0; nf < 8; nf++)
                #pragma unroll
                for (int rr = 0; rr < 2; rr++) {
                    float2 v = h2f2(acc[mf][nf][rr]);
                    int i0 = nf * 2, i1 = nf * 2 + 1;
                    float E0 = fabsf(fmaf(v.x, -CC, sColv[i0]));
                    float E1 = fabsf(fmaf(v.y, -CC, sColv[i1]));
                    if (E0 > McF[i0] - SKIP_T) cS[i0] += ex2f(E0 - McF[i0]);
                    if (E1 > McF[i1] - SKIP_T) cS[i1] += ex2f(E1 - McF[i1]);
                }
        #pragma unroll
        for (int ii = 0; ii < 16; ii++) {
            cS[ii] += __shfl_xor_sync(0xFFFFFFFFu, cS[ii], 4);
            cS[ii] += __shfl_xor_sync(0xFFFFFFFFu, cS[ii], 8);
            cS[ii] += __shfl_xor_sync(0xFFFFFFFFu, cS[ii], 16);
        }
        if (lane < 4) {
            #pragma unroll
            for (int ii = 0; ii < 16; ii++)
                colSbuf[wr * 128 + wc * 64 + (ii >> 1) * 8 + lane * 2 + (ii & 1)] = cS[ii];
        }
        __syncthreads();
        if (wr == 0) {
            #pragma unroll
            for (int rep = 0; rep < 2; rep++) {
                int cl = wc * 64 + lane + rep * 32;
                float S = colSbuf[cl] + colSbuf[128 + cl] +
                          colSbuf[256 + cl] + colSbuf[384 + cl];
                g_c[(size_t)(col0 + cl) * NTILES + I] = make_float2(colMF[cl], S);
            }
        }
    }
}

// ---------------- K3: warp-per-row combine + global finisher (R10) ----------
__global__ void k3_rows(float* __restrict__ out, int n, int ntiles) {
    int wid = threadIdx.x >> 5, lane = threadIdx.x & 31;
    int warpg = blockIdx.x * 8 + wid;
    float acc = 0.f;
    #pragma unroll
    for (int r = 0; r < 8; r++) {
        int row = warpg * 8 + r;
        float4 v = reinterpret_cast<const float4*>(g_c + (size_t)row * NTILES)[lane];
        float m = fmaxf(v.x, v.z);
        #pragma unroll
        for (int o = 16; o; o >>= 1) m = fmaxf(m, __shfl_xor_sync(0xFFFFFFFFu, m, o));
        float S = 0.f;
        if (v.x > m - 33.f) S += v.y * ex2f(v.x - m);
        if (v.z > m - 33.f) S += v.w * ex2f(v.z - m);
        #pragma unroll
        for (int o = 16; o; o >>= 1) S += __shfl_xor_sync(0xFFFFFFFFu, S, o);
        if (lane == 0) acc += (m + lg2f(S)) - g_dlabE[row];
    }
    __shared__ float red[8];
    if (lane == 0) red[wid] = acc;
    __syncthreads();
    if (threadIdx.x == 0) {
        float s = 0.f;
        #pragma unroll
        for (int kk = 0; kk < 8; kk++) s += red[kk];
        atomicAdd(&g_sum, s);
        __threadfence();
        int c = atomicAdd(&g_count, 1);
        if (c == (int)gridDim.x - 1)
            out[0] = g_sum * (LN2F / (float)n);
    }
}

// ---------------- launch ----------------
extern "C" void kernel_launch(void* const* d_in, const int* in_sizes, int n_in,
                              void* d_out, int out_size) {
    const float* q     = (const float*)d_in[0];
    const float* t     = (const float*)d_in[1];
    const int*   label = (const int*)d_in[2];
    const int*   jidx  = (const int*)d_in[3];
    int n = in_sizes[2];                     // 8192
    int ntiles = n / TM;                     // 64
    int pairs = ntiles * (ntiles + 1) / 2;   // 2080

    cudaFuncSetAttribute(k2_sym, cudaFuncAttributeMaxDynamicSharedMemorySize, SMEM_K2);

    k1_rowprep<<<n / 8, 256>>>(q, t, label, jidx, n);
    k2_sym<<<pairs, 256, SMEM_K2>>>(ntiles);
    k3_rows<<<n / 64, 256>>>((float*)d_out, n, ntiles);
}

// round 17
// speedup vs baseline: 1.3514x; 1.3514x over previous
#include <cuda_runtime.h>
#include <cuda_fp16.h>
#include <cstdint>

// ---------------- problem constants ----------------
#define NMAX    8192
#define DDIM    128
#define TM      128
#define NTILES  (NMAX / TM)           // 64
#define CC      14.426950408889634f   // log2(e) / TEMPERATURE(=0.1)
#define LN2F    0.69314718055994531f
#define SKIP_T  25.0f

#define TILE_BYTES (TM * DDIM * 2)    // 32 KB fp16

// smem layout (bytes)
#define OFF_A     0
#define OFF_B     (TILE_BYTES)
#define OFF_SROW  (2 * TILE_BYTES)            // 128 f32
#define OFF_SCOL  (OFF_SROW + 512)            // 128 f32
#define OFF_ROWMM (OFF_SCOL + 512)            // 2 x 128 float2 (rawmax, rawmin)
#define OFF_ROWS  (OFF_ROWMM + 2048)          // 2 x 128 f32
#define OFF_COLMM (OFF_ROWS + 1024)           // 4 x 128 float2
#define OFF_COLMF (OFF_COLMM + 4096)          // 128 f32
#define OFF_COLS  (OFF_COLMF + 512)           // 4 x 128 f32
#define SMEM_K2   (OFF_COLS + 2048)           // 76288

__device__ __align__(16) __half g_thf[NMAX * DDIM];   // t in fp16
__device__ float  g_sC[NMAX];             // s_i * CC
__device__ float  g_dlabE[NMAX];          // |s_i - u_i| * CC
__device__ __align__(16) float2 g_c[NMAX * NTILES];   // [row][slot] = (max, sum)
__device__ float  g_sum;
__device__ int    g_count;

// ---------------- low-level helpers ----------------
__device__ __forceinline__ float ex2f(float x) {
    float r;
    asm("ex2.approx.f32 %0, %1;" : "=f"(r) : "f"(x));
    return r;
}
__device__ __forceinline__ float lg2f(float x) {
    float r;
    asm("lg2.approx.f32 %0, %1;" : "=f"(r) : "f"(x));
    return r;
}
__device__ __forceinline__ uint32_t smem_u32(const void* p) {
    uint32_t a;
    asm("{ .reg .u64 t; cvta.to.shared.u64 t, %1; cvt.u32.u64 %0, t; }" : "=r"(a) : "l"(p));
    return a;
}
__device__ __forceinline__ void cp_async16(uint32_t dst, const void* src) {
    asm volatile("cp.async.cg.shared.global [%0], [%1], 16;" :: "r"(dst), "l"(src) : "memory");
}
#define CP_COMMIT() asm volatile("cp.async.commit_group;" ::: "memory")
#define CP_WAIT0()  asm volatile("cp.async.wait_group 0;" ::: "memory")

#define LDSM_X4(r, addr)                                                      \
    asm volatile("ldmatrix.sync.aligned.m8n8.x4.shared.b16 {%0,%1,%2,%3}, [%4];" \
        : "=r"((r)[0]), "=r"((r)[1]), "=r"((r)[2]), "=r"((r)[3]) : "r"(addr))

// fp16 inputs, fp16 accumulators (2 b32 regs = 4 halves)
__device__ __forceinline__ void mma16816h(uint32_t* c, const uint32_t* a,
                                          uint32_t b0, uint32_t b1) {
    asm volatile(
        "mma.sync.aligned.m16n8k16.row.col.f16.f16.f16.f16 "
        "{%0,%1}, {%2,%3,%4,%5}, {%6,%7}, {%0,%1};"
        : "+r"(c[0]), "+r"(c[1])
        : "r"(a[0]), "r"(a[1]), "r"(a[2]), "r"(a[3]), "r"(b0), "r"(b1));
}
__device__ __forceinline__ uint32_t swz(int r, int c) {
    return (uint32_t)(r * 256 + ((c ^ (r & 7)) << 4));
}
__device__ __forceinline__ float2 h2f2(uint32_t h) {
    return __half22float2(*reinterpret_cast<__half2*>(&h));
}
__device__ __forceinline__ __half2 u2h2(uint32_t h) {
    return *reinterpret_cast<__half2*>(&h);
}
__device__ __forceinline__ __half2 shfl_hmax2(__half2 v, int off) {
    uint32_t u = *reinterpret_cast<uint32_t*>(&v);
    u = __shfl_xor_sync(0xFFFFFFFFu, u, off);
    return __hmax2(v, *reinterpret_cast<__half2*>(&u));
}
__device__ __forceinline__ __half2 shfl_hmin2(__half2 v, int off) {
    uint32_t u = *reinterpret_cast<uint32_t*>(&v);
    u = __shfl_xor_sync(0xFFFFFFFFu, u, off);
    return __hmin2(v, *reinterpret_cast<__half2*>(&u));
}

// ---------------- K1: per-row scalars + t -> fp16 (R10 verbatim) ----------
__global__ void k1_rowprep(const float* __restrict__ q, const float* __restrict__ t,
                           const int* __restrict__ label, const int* __restrict__ jidx,
                           int n) {
    if (blockIdx.x == 0 && threadIdx.x == 0) { g_sum = 0.f; g_count = 0; }
    int i = blockIdx.x * 8 + (threadIdx.x >> 5);
    if (i >= n) return;
    int lane = threadIdx.x & 31;
    int j = jidx[i];

    float4 a = reinterpret_cast<const float4*>(q + (size_t)i * DDIM)[lane];
    float4 b = reinterpret_cast<const float4*>(q + (size_t)j * DDIM)[lane];
    float s = a.x * b.x + a.y * b.y + a.z * b.z + a.w * b.w;
    #pragma unroll
    for (int o = 16; o; o >>= 1) s += __shfl_xor_sync(0xFFFFFFFFu, s, o);

    int l = label[i];
    int col;
    if (l == i)       col = j;
    else if (j > i)   col = (l > i && l <= j) ? l - 1 : l;
    else              col = (l >= j && l < i) ? l + 1 : l;

    float4 c = reinterpret_cast<const float4*>(t + (size_t)i   * DDIM)[lane];
    float4 d = reinterpret_cast<const float4*>(t + (size_t)col * DDIM)[lane];
    float u = c.x * d.x + c.y * d.y + c.z * d.z + c.w * d.w;
    #pragma unroll
    for (int o = 16; o; o >>= 1) u += __shfl_xor_sync(0xFFFFFFFFu, u, o);

    __half2 p0 = __floats2half2_rn(c.x, c.y);
    __half2 p1 = __floats2half2_rn(c.z, c.w);
    uint2 pk;
    pk.x = *reinterpret_cast<uint32_t*>(&p0);
    pk.y = *reinterpret_cast<uint32_t*>(&p1);
    reinterpret_cast<uint2*>(g_thf + (size_t)i * DDIM)[lane] = pk;

    if (lane == 0) {
        g_sC[i]    = s * CC;
        g_dlabE[i] = fabsf(s - u) * CC;
    }
}

// ---------------- K2: R10 + packed raw-minmax pass-1 ----------------
__global__ void __launch_bounds__(256, 2) k2_sym(int ntiles) {
    extern __shared__ char smem[];
    const int tid = threadIdx.x, wid = tid >> 5, lane = tid & 31;
    const int wr = wid & 3;          // warp row group (32 rows)
    const int wc = wid >> 2;         // warp col group (64 cols)
    const int g = lane >> 2, tig = lane & 3;

    // decode blockIdx -> (I, J), I <= J
    int b = blockIdx.x;
    int I;
    {
        float nn = 2.0f * ntiles + 1.0f;
        I = (int)((nn - sqrtf(nn * nn - 8.0f * (float)b)) * 0.5f);
        if (I < 0) I = 0;
        while ((I + 1) * ntiles - ((I + 1) * I) / 2 <= b) ++I;
        while (I * ntiles - (I * (I - 1)) / 2 > b) --I;
    }
    const int J = I + (b - (I * ntiles - (I * (I - 1)) / 2));
    const bool diag = (I == J);
    const int row0 = I * TM, col0 = J * TM;

    const uint32_t sA = smem_u32(smem);
    const uint32_t sB = diag ? sA : (sA + OFF_B);
    float*  sRowBuf = reinterpret_cast<float*>(smem + OFF_SROW);
    float*  sColBuf = reinterpret_cast<float*>(smem + OFF_SCOL);
    float2* rowMM   = reinterpret_cast<float2*>(smem + OFF_ROWMM);
    float*  rowSbuf = reinterpret_cast<float*>(smem + OFF_ROWS);
    float2* colMM   = reinterpret_cast<float2*>(smem + OFF_COLMM);
    float*  colMF   = reinterpret_cast<float*>(smem + OFF_COLMF);
    float*  colSbuf = reinterpret_cast<float*>(smem + OFF_COLS);

    // ---- stage tiles + s vectors ----
    {
        const char* Ag = (const char*)(g_thf + (size_t)row0 * DDIM);
        for (int idx = tid; idx < 2048; idx += 256)
            cp_async16(sA + swz(idx >> 4, idx & 15), Ag + idx * 16);
        if (!diag) {
            const char* Bg = (const char*)(g_thf + (size_t)col0 * DDIM);
            for (int idx = tid; idx < 2048; idx += 256)
                cp_async16(sA + OFF_B + swz(idx >> 4, idx & 15), Bg + idx * 16);
        }
        if (tid < 128) sRowBuf[tid] = g_sC[row0 + tid];
        else           sColBuf[tid - 128] = g_sC[col0 + tid - 128];
        CP_COMMIT();
        CP_WAIT0();
        __syncthreads();
    }

    // ---- 128x128x128 MMA: warp does 32x64, frags 2(M) x 8(N), fp16 acc ----
    uint32_t acc[2][8][2];
    #pragma unroll
    for (int mf = 0; mf < 2; mf++)
        #pragma unroll
        for (int nf = 0; nf < 8; nf++) {
            acc[mf][nf][0] = 0u;
            acc[mf][nf][1] = 0u;
        }

    #pragma unroll
    for (int kc = 0; kc < 8; kc++) {
        uint32_t a0[4], a1[4];
        {
            int r = wr * 32 + (lane & 15);
            int c = kc * 2 + (lane >> 4);
            LDSM_X4(a0, sA + swz(r, c));
            LDSM_X4(a1, sA + swz(r + 16, c));
        }
        #pragma unroll
        for (int p = 0; p < 4; p++) {
            uint32_t bb[4];
            int r = wc * 64 + p * 16 + ((lane >> 4) << 3) + (lane & 7);
            int c = kc * 2 + ((lane >> 3) & 1);
            LDSM_X4(bb, sB + swz(r, c));
            mma16816h(acc[0][2 * p],     a0, bb[0], bb[1]);
            mma16816h(acc[0][2 * p + 1], a0, bb[2], bb[3]);
            mma16816h(acc[1][2 * p],     a1, bb[0], bb[1]);
            mma16816h(acc[1][2 * p + 1], a1, bb[2], bb[3]);
        }
    }

    // frag coords: reg rr (0/1): row_local = wr*32 + mf*16 + rr*8 + g
    //              half h (lo/hi): col_local = wc*64 + nf*8 + tig*2 + h

    // ======== PASS 1: packed raw max/min (serves BOTH directions) ========
    const __half2 H2LO = __float2half2_rn(-60000.f);
    const __half2 H2HI = __float2half2_rn(60000.f);
    __half2 rmax2[4], rmin2[4];      // per row-position qq (halves = 2 cols, merged later)
    __half2 cmax2[8], cmin2[8];      // per nf (halves = 2 distinct cols, kept separate)
    #pragma unroll
    for (int qq = 0; qq < 4; qq++) { rmax2[qq] = H2LO; rmin2[qq] = H2HI; }
    #pragma unroll
    for (int nf = 0; nf < 8; nf++) { cmax2[nf] = H2LO; cmin2[nf] = H2HI; }
    #pragma unroll
    for (int mf = 0; mf < 2; mf++)
        #pragma unroll
        for (int nf = 0; nf < 8; nf++)
            #pragma unroll
            for (int rr = 0; rr < 2; rr++) {
                __half2 a2 = u2h2(acc[mf][nf][rr]);
                int qq = mf * 2 + rr;
                rmax2[qq] = __hmax2(rmax2[qq], a2);
                rmin2[qq] = __hmin2(rmin2[qq], a2);
                cmax2[nf] = __hmax2(cmax2[nf], a2);
                cmin2[nf] = __hmin2(cmin2[nf], a2);
            }
    // row: merge across tig (packed), then unpack halves
    #pragma unroll
    for (int qq = 0; qq < 4; qq++) {
        rmax2[qq] = shfl_hmax2(rmax2[qq], 1);
        rmax2[qq] = shfl_hmax2(rmax2[qq], 2);
        rmin2[qq] = shfl_hmin2(rmin2[qq], 1);
        rmin2[qq] = shfl_hmin2(rmin2[qq], 2);
    }
    float rawMax[4], rawMin[4];
    #pragma unroll
    for (int qq = 0; qq < 4; qq++) {
        rawMax[qq] = fmaxf(__low2float(rmax2[qq]), __high2float(rmax2[qq]));
        rawMin[qq] = fminf(__low2float(rmin2[qq]), __high2float(rmin2[qq]));
    }
    if (tig == 0) {
        #pragma unroll
        for (int qq = 0; qq < 4; qq++) {
            int rl = wr * 32 + (qq >> 1) * 16 + (qq & 1) * 8 + g;
            rowMM[wc * 128 + rl] = make_float2(rawMax[qq], rawMin[qq]);
        }
    }
    // col: merge across g (packed shuffles 4,8,16), lanes<4 write unpacked
    #pragma unroll
    for (int nf = 0; nf < 8; nf++) {
        cmax2[nf] = shfl_hmax2(cmax2[nf], 4);
        cmax2[nf] = shfl_hmax2(cmax2[nf], 8);
        cmax2[nf] = shfl_hmax2(cmax2[nf], 16);
        cmin2[nf] = shfl_hmin2(cmin2[nf], 4);
        cmin2[nf] = shfl_hmin2(cmin2[nf], 8);
        cmin2[nf] = shfl_hmin2(cmin2[nf], 16);
    }
    if (!diag && lane < 4) {
        #pragma unroll
        for (int nf = 0; nf < 8; nf++) {
            int cl = wc * 64 + nf * 8 + lane * 2;
            colMM[wr * 128 + cl]     = make_float2(__low2float(cmax2[nf]),  __low2float(cmin2[nf]));
            colMM[wr * 128 + cl + 1] = make_float2(__high2float(cmax2[nf]), __high2float(cmin2[nf]));
        }
    }
    __syncthreads();

    // ---- per-column M (wid 0 & 4 compute 64 cols each) ----
    if (!diag && wr == 0) {
        #pragma unroll
        for (int rep = 0; rep < 2; rep++) {
            int cl = wc * 64 + lane + rep * 32;
            float2 v0 = colMM[cl], v1 = colMM[128 + cl];
            float2 v2 = colMM[256 + cl], v3 = colMM[384 + cl];
            float mx = fmaxf(fmaxf(v0.x, v1.x), fmaxf(v2.x, v3.x));
            float mn = fminf(fminf(v0.y, v1.y), fminf(v2.y, v3.y));
            float sc = sColBuf[cl];
            colMF[cl] = fmaxf(fmaf(mx, CC, -sc), fmaf(mn, -CC, sc));
        }
    }
    __syncthreads();

    // ---- row thresholds ----
    float sRow[4], Mrow[4], rS[4];
    #pragma unroll
    for (int qq = 0; qq < 4; qq++) {
        int rl = wr * 32 + (qq >> 1) * 16 + (qq & 1) * 8 + g;
        float2 o = rowMM[(1 - wc) * 128 + rl];
        float amax = fmaxf(rawMax[qq], o.x);
        float amin = fminf(rawMin[qq], o.y);
        float s = sRowBuf[rl];
        sRow[qq] = s;
        Mrow[qq] = fmaxf(fmaf(amax, CC, -s), fmaf(amin, -CC, s));
        rS[qq] = 0.f;
    }

    // ======== PASS 2 (row): dense guarded scan — identical to R10 ========
    #pragma unroll
    for (int mf = 0; mf < 2; mf++)
        #pragma unroll
        for (int nf = 0; nf < 8; nf++)
            #pragma unroll
            for (int rr = 0; rr < 2; rr++) {
                int qq = mf * 2 + rr;
                float2 v = h2f2(acc[mf][nf][rr]);
                float E0 = fabsf(fmaf(v.x, -CC, sRow[qq]));
                float E1 = fabsf(fmaf(v.y, -CC, sRow[qq]));
                if (E0 > Mrow[qq] - SKIP_T) rS[qq] += ex2f(E0 - Mrow[qq]);
                if (E1 > Mrow[qq] - SKIP_T) rS[qq] += ex2f(E1 - Mrow[qq]);
            }
    #pragma unroll
    for (int qq = 0; qq < 4; qq++) {
        rS[qq] += __shfl_xor_sync(0xFFFFFFFFu, rS[qq], 1);
        rS[qq] += __shfl_xor_sync(0xFFFFFFFFu, rS[qq], 2);
    }
    if (tig == 0) {
        #pragma unroll
        for (int qq = 0; qq < 4; qq++)
            rowSbuf[wc * 128 + wr * 32 + (qq >> 1) * 16 + (qq & 1) * 8 + g] = rS[qq];
    }
    __syncthreads();
    if (wc == 0 && tig == 0) {
        #pragma unroll
        for (int qq = 0; qq < 4; qq++) {
            int rl = wr * 32 + (qq >> 1) * 16 + (qq & 1) * 8 + g;
            float S = rS[qq] + rowSbuf[128 + rl];
            g_c[(size_t)(row0 + rl) * NTILES + J] = make_float2(Mrow[qq], S);
        }
    }

    // ======== PASS 2 (col): dense guarded scan — identical to R10 ========
    if (!diag) {
        float sColv[16], cS[16], McF[16];
        #pragma unroll
        for (int nf = 0; nf < 8; nf++)
            #pragma unroll
            for (int p = 0; p < 2; p++) {
                int cl = wc * 64 + nf * 8 + tig * 2 + p;
                sColv[nf * 2 + p] = sColBuf[cl];
                McF[nf * 2 + p] = colMF[cl];
                cS[nf * 2 + p] = 0.f;
            }
        #pragma unroll
        for (int mf = 0; mf < 2; mf++)
            #pragma unroll
            for (int nf = 0; nf < 8; nf++)
                #pragma unroll
                for (int rr = 0; rr < 2; rr++) {
                    float2 v = h2f2(acc[mf][nf][rr]);
                    int i0 = nf * 2, i1 = nf * 2 + 1;
                    float E0 = fabsf(fmaf(v.x, -CC, sColv[i0]));
                    float E1 = fabsf(fmaf(v.y, -CC, sColv[i1]));
                    if (E0 > McF[i0] - SKIP_T) cS[i0] += ex2f(E0 - McF[i0]);
                    if (E1 > McF[i1] - SKIP_T) cS[i1] += ex2f(E1 - McF[i1]);
                }
        #pragma unroll
        for (int ii = 0; ii < 16; ii++) {
            cS[ii] += __shfl_xor_sync(0xFFFFFFFFu, cS[ii], 4);
            cS[ii] += __shfl_xor_sync(0xFFFFFFFFu, cS[ii], 8);
            cS[ii] += __shfl_xor_sync(0xFFFFFFFFu, cS[ii], 16);
        }
        if (lane < 4) {
            #pragma unroll
            for (int ii = 0; ii < 16; ii++)
                colSbuf[wr * 128 + wc * 64 + (ii >> 1) * 8 + lane * 2 + (ii & 1)] = cS[ii];
        }
        __syncthreads();
        if (wr == 0) {
            #pragma unroll
            for (int rep = 0; rep < 2; rep++) {
                int cl = wc * 64 + lane + rep * 32;
                float S = colSbuf[cl] + colSbuf[128 + cl] +
                          colSbuf[256 + cl] + colSbuf[384 + cl];
                g_c[(size_t)(col0 + cl) * NTILES + I] = make_float2(colMF[cl], S);
            }
        }
    }
}

// ---------------- K3: warp-per-row combine + global finisher (R10) ----------
__global__ void k3_rows(float* __restrict__ out, int n, int ntiles) {
    int wid = threadIdx.x >> 5, lane = threadIdx.x & 31;
    int warpg = blockIdx.x * 8 + wid;
    float acc = 0.f;
    #pragma unroll
    for (int r = 0; r < 8; r++) {
        int row = warpg * 8 + r;
        float4 v = reinterpret_cast<const float4*>(g_c + (size_t)row * NTILES)[lane];
        float m = fmaxf(v.x, v.z);
        #pragma unroll
        for (int o = 16; o; o >>= 1) m = fmaxf(m, __shfl_xor_sync(0xFFFFFFFFu, m, o));
        float S = 0.f;
        if (v.x > m - 33.f) S += v.y * ex2f(v.x - m);
        if (v.z > m - 33.f) S += v.w * ex2f(v.z - m);
        #pragma unroll
        for (int o = 16; o; o >>= 1) S += __shfl_xor_sync(0xFFFFFFFFu, S, o);
        if (lane == 0) acc += (m + lg2f(S)) - g_dlabE[row];
    }
    __shared__ float red[8];
    if (lane == 0) red[wid] = acc;
    __syncthreads();
    if (threadIdx.x == 0) {
        float s = 0.f;
        #pragma unroll
        for (int kk = 0; kk < 8; kk++) s += red[kk];
        atomicAdd(&g_sum, s);
        __threadfence();
        int c = atomicAdd(&g_count, 1);
        if (c == (int)gridDim.x - 1)
            out[0] = g_sum * (LN2F / (float)n);
    }
}

// ---------------- launch ----------------
extern "C" void kernel_launch(void* const* d_in, const int* in_sizes, int n_in,
                              void* d_out, int out_size) {
    const float* q     = (const float*)d_in[0];
    const float* t     = (const float*)d_in[1];
    const int*   label = (const int*)d_in[2];
    const int*   jidx  = (const int*)d_in[3];
    int n = in_sizes[2];                     // 8192
    int ntiles = n / TM;                     // 64
    int pairs = ntiles * (ntiles + 1) / 2;   // 2080

    cudaFuncSetAttribute(k2_sym, cudaFuncAttributeMaxDynamicSharedMemorySize, SMEM_K2);

    k1_rowprep<<<n / 8, 256>>>(q, t, label, jidx, n);
    k2_sym<<<pairs, 256, SMEM_K2>>>(ntiles);
    k3_rows<<<n / 64, 256>>>((float*)d_out, n, ntiles);
}